// round 3
// baseline (speedup 1.0000x reference)
#include <cuda_runtime.h>
#include <cuda_bf16.h>
#include <cstdint>

// FeatureBank fused: out = memory, except rows y[i] get normalize(0.5*memory[y[i]] + 0.5*x[i])
//
// Inputs: x [4096,128] f32, y [4096] int32, memory [500000,128] f32
// Output: new_memory [500000,128] f32
//
// Three graph-capturable kernels on one stream:
//   1. scatter:  map[y[i]] = i+1
//   2. fused:    warp-per-row streaming copy; dirty rows take blend+normalize path
//   3. reset:    map[y[i]] = 0   (keeps map all-zero for the next replay; deterministic)

#define MOMENTUM 0.5f
#define DIM 128
#define BATCH 4096
#define N_ROWS 500000

__device__ int g_row_map[N_ROWS];  // zero-initialized .bss; invariant: all zeros outside a launch

__global__ void scatter_map_kernel(const int* __restrict__ y) {
    int i = blockIdx.x * blockDim.x + threadIdx.x;
    if (i < BATCH) g_row_map[y[i]] = i + 1;
}

__global__ void reset_map_kernel(const int* __restrict__ y) {
    int i = blockIdx.x * blockDim.x + threadIdx.x;
    if (i < BATCH) g_row_map[y[i]] = 0;
}

// One warp per row. Lane l handles the float4 at dim offset l*4 (32*16B = 512B/row).
__global__ void __launch_bounds__(256) fused_copy_update_kernel(
        const float* __restrict__ x,
        const float* __restrict__ memory,
        float* __restrict__ out) {
    int warp_id = (blockIdx.x * blockDim.x + threadIdx.x) >> 5;
    int lane = threadIdx.x & 31;
    if (warp_id >= N_ROWS) return;

    int m = 0;
    if (lane == 0) m = g_row_map[warp_id];
    m = __shfl_sync(0xFFFFFFFFu, m, 0);

    const float4* src = reinterpret_cast<const float4*>(memory + (size_t)warp_id * DIM);
    float4*       dst = reinterpret_cast<float4*>(out + (size_t)warp_id * DIM);

    float4 mv = src[lane];

    if (m == 0) {
        // clean row: straight copy
        dst[lane] = mv;
    } else {
        // dirty row: EMA blend with x[m-1], L2-normalize
        const float4* xr = reinterpret_cast<const float4*>(x + (size_t)(m - 1) * DIM);
        float4 xv = xr[lane];

        float4 w;
        w.x = mv.x * MOMENTUM + xv.x * (1.0f - MOMENTUM);
        w.y = mv.y * MOMENTUM + xv.y * (1.0f - MOMENTUM);
        w.z = mv.z * MOMENTUM + xv.z * (1.0f - MOMENTUM);
        w.w = mv.w * MOMENTUM + xv.w * (1.0f - MOMENTUM);

        float ss = w.x * w.x + w.y * w.y + w.z * w.z + w.w * w.w;
        #pragma unroll
        for (int off = 16; off > 0; off >>= 1)
            ss += __shfl_xor_sync(0xFFFFFFFFu, ss, off);

        float inv = rsqrtf(ss);

        float4 o;
        o.x = w.x * inv;
        o.y = w.y * inv;
        o.z = w.z * inv;
        o.w = w.w * inv;
        dst[lane] = o;
    }
}

extern "C" void kernel_launch(void* const* d_in, const int* in_sizes, int n_in,
                              void* d_out, int out_size) {
    const float* x      = (const float*)d_in[0];
    const int*   y      = (const int*)d_in[1];
    const float* memory = (const float*)d_in[2];
    float*       out    = (float*)d_out;

    // 1. mark dirty rows
    scatter_map_kernel<<<(BATCH + 255) / 256, 256>>>(y);

    // 2. fused stream: 500000 warps, 8 warps/block -> 62500 blocks
    fused_copy_update_kernel<<<(N_ROWS * 32 + 255) / 256, 256>>>(x, memory, out);

    // 3. restore map to all-zero for the next (graph-replayed) call
    reset_map_kernel<<<(BATCH + 255) / 256, 256>>>(y);
}